// round 4
// baseline (speedup 1.0000x reference)
#include <cuda_runtime.h>

#define SEQ   512
#define BATCH 4096
#define HID   30
#define HROW  32   // ull entries per (buf,b) row: 30 used + 2 pad

typedef unsigned long long ull;

__device__ __forceinline__ ull pk2(float a, float b) {
    ull r; asm("mov.b64 %0,{%1,%2};" : "=l"(r) : "f"(a), "f"(b)); return r;
}
__device__ __forceinline__ void unpk2(ull v, float& a, float& b) {
    asm("mov.b64 {%0,%1},%2;" : "=f"(a), "=f"(b) : "l"(v));
}
// Packed dual-fp32 FMA / ADD (Blackwell f32x2) — 2 lanes of fp32 per issue.
__device__ __forceinline__ ull ffma2(ull a, ull b, ull c) {
    ull d; asm("fma.rn.f32x2 %0,%1,%2,%3;" : "=l"(d) : "l"(a), "l"(b), "l"(c)); return d;
}
__device__ __forceinline__ ull add2(ull a, ull b) {
    ull d; asm("add.rn.f32x2 %0,%1,%2;" : "=l"(d) : "l"(a), "l"(b)); return d;
}

// tanh(x) = 1 - 2/(exp2(2x*log2e)+1); ex2/rcp approx -> ~1e-7 abs error.
__device__ __forceinline__ float tanhfast(float x) {
    float e, r;
    asm("ex2.approx.f32 %0, %1;" : "=f"(e) : "f"(x * 2.8853900817779268f));
    asm("rcp.approx.f32 %0, %1;" : "=f"(r) : "f"(e + 1.0f));
    return fmaf(-2.0f, r, 1.0f);
}

#define NWARP 4   // warps per CTA -> spreads across all 4 SMSPs (wid % 4)

__global__ void __launch_bounds__(32 * NWARP)
rnn_kernel(const float* __restrict__ X,     const float* __restrict__ W_ih,
           const float* __restrict__ W_hh,  const float* __restrict__ b_ih,
           const float* __restrict__ b_hh,  const float* __restrict__ W_out,
           const float* __restrict__ b_out, float* __restrict__ Y)
{
    // Per-warp h double buffer, DUPLICATED: hbuf[w][buf][b][k] = (h[k], h[k])
    __shared__ __align__(16) ull hbuf[NWARP][2][2][HROW];

    const int wid  = threadIdx.x >> 5;
    const int lane = threadIdx.x & 31;
    const int jp   = lane & 15;            // hidden-unit pair index
    const int b    = lane >> 4;            // which of this warp's 2 batches
    const int j0   = 2 * jp, j1 = j0 + 1;
    const int batch = blockIdx.x * (2 * NWARP) + wid * 2 + b;

    // ---- weights in registers, packed over (j0, j1) ----
    ull w2[HID];
#pragma unroll
    for (int k = 0; k < HID; k++) {
        float a = (j0 < HID) ? W_hh[j0 * HID + k] : 0.0f;
        float c = (j1 < HID) ? W_hh[j1 * HID + k] : 0.0f;
        w2[k] = pk2(a, c);
    }
    const ull wih2 = pk2((j0 < HID) ? W_ih[j0] : 0.0f,
                         (j1 < HID) ? W_ih[j1] : 0.0f);
    const ull bias2 = pk2((j0 < HID) ? (b_ih[j0] + b_hh[j0]) : 0.0f,
                          (j1 < HID) ? (b_ih[j1] + b_hh[j1]) : 0.0f);
    const float wo0 = (j0 < HID) ? W_out[j0] : 0.0f;
    const float wo1 = (j1 < HID) ? W_out[j1] : 0.0f;
    const float bo  = b_out[0];

    // ---- h0 = 0 ----
    hbuf[wid][0][b][j0] = 0ull;
    hbuf[wid][0][b][j1] = 0ull;
    __syncwarp();

    const float* Xb = X + batch;
    float*       Yb = Y + batch;

    float pp = 0.0f;                 // y partial, reduced one step late
    float xcur = Xb[0];              // x prefetch pipeline

    for (int s = 0; s < SEQ; s++) {
        const ull* hc = &hbuf[wid][s & 1][b][0];
        ull*       hn = &hbuf[wid][(s & 1) ^ 1][b][0];

        // ---- previous step's y: butterfly-reduce within each 16-lane half ----
        if (s > 0) {
            float r = pp;
#pragma unroll
            for (int m = 1; m < 16; m <<= 1)
                r += __shfl_xor_sync(0xffffffffu, r, m);
            if (jp == 0) Yb[(s - 1) * BATCH] = r + bo;
        }

        // ---- start next x load (latency hidden under this step) ----
        const float xc = xcur;
        if (s + 1 < SEQ) xcur = Xb[(s + 1) * BATCH];

        // ---- matvec with 4 split accumulator chains ----
        ull a0 = bias2, a1 = 0ull, a2 = 0ull, a3 = 0ull;
#pragma unroll
        for (int i = 0; i < 15; i++) {
            ulonglong2 hv = *(const ulonglong2*)&hc[2 * i];   // (dup h[2i], dup h[2i+1])
            if (i & 1) {
                a2 = ffma2(w2[2 * i],     hv.x, a2);
                a3 = ffma2(w2[2 * i + 1], hv.y, a3);
            } else {
                a0 = ffma2(w2[2 * i],     hv.x, a0);
                a1 = ffma2(w2[2 * i + 1], hv.y, a1);
            }
        }
        a0 = ffma2(wih2, pk2(xc, xc), a0);
        const ull acc = add2(add2(a0, a2), add2(a1, a3));

        // ---- tanh ----
        float v0, v1;
        unpk2(acc, v0, v1);
        const float h0 = tanhfast(v0);
        const float h1 = tanhfast(v1);

        // ---- publish h_{s+1}: one STS.128, duplicated layout ----
        ulonglong2 st;
        st.x = pk2(h0, h0);
        st.y = pk2(h1, h1);
        *(ulonglong2*)&hn[j0] = st;

        // ---- this step's y partial (reduced next iteration) ----
        pp = fmaf(h0, wo0, h1 * wo1);

        __syncwarp();
    }

    // final step's y
    {
        float r = pp;
#pragma unroll
        for (int m = 1; m < 16; m <<= 1)
            r += __shfl_xor_sync(0xffffffffu, r, m);
        if (jp == 0) Yb[(SEQ - 1) * BATCH] = r + bo;
    }
}

extern "C" void kernel_launch(void* const* d_in, const int* in_sizes, int n_in,
                              void* d_out, int out_size)
{
    (void)in_sizes; (void)n_in; (void)out_size;
    rnn_kernel<<<BATCH / (2 * NWARP), 32 * NWARP>>>(
        (const float*)d_in[0],  // X
        (const float*)d_in[1],  // W_ih
        (const float*)d_in[2],  // W_hh
        (const float*)d_in[3],  // b_ih
        (const float*)d_in[4],  // b_hh
        (const float*)d_in[5],  // W_out
        (const float*)d_in[6],  // b_out
        (float*)d_out);
}

// round 5
// speedup vs baseline: 1.2642x; 1.2642x over previous
#include <cuda_runtime.h>

#define SEQ   512
#define BATCH 4096
#define HID   30
#define HROW  34   // ull entries per (buf,b) row: 30 used + pad -> b0/b1 rows on disjoint banks
#define PF    8    // X prefetch depth (outstanding LDGs per thread)

typedef unsigned long long ull;

__device__ __forceinline__ ull pk2(float a, float b) {
    ull r; asm("mov.b64 %0,{%1,%2};" : "=l"(r) : "f"(a), "f"(b)); return r;
}
__device__ __forceinline__ void unpk2(ull v, float& a, float& b) {
    asm("mov.b64 {%0,%1},%2;" : "=f"(a), "=f"(b) : "l"(v));
}
// Packed dual-fp32 FMA / ADD (Blackwell f32x2) — 2 lanes of fp32 per issue.
__device__ __forceinline__ ull ffma2(ull a, ull b, ull c) {
    ull d; asm("fma.rn.f32x2 %0,%1,%2,%3;" : "=l"(d) : "l"(a), "l"(b), "l"(c)); return d;
}
__device__ __forceinline__ ull add2(ull a, ull b) {
    ull d; asm("add.rn.f32x2 %0,%1,%2;" : "=l"(d) : "l"(a), "l"(b)); return d;
}

// tanh with PRE-SCALED input: v = 2*log2(e)*z already (factor folded into weights).
// tanh(z) = 1 - 2/(exp2(v)+1); ex2/rcp approx -> ~1e-7 abs error.
__device__ __forceinline__ float tanh_ps(float v) {
    float e, r;
    asm("ex2.approx.f32 %0, %1;" : "=f"(e) : "f"(v));
    asm("rcp.approx.f32 %0, %1;" : "=f"(r) : "f"(e + 1.0f));
    return fmaf(-2.0f, r, 1.0f);
}

__global__ void __launch_bounds__(32)
rnn_kernel(const float* __restrict__ X,     const float* __restrict__ W_ih,
           const float* __restrict__ W_hh,  const float* __restrict__ b_ih,
           const float* __restrict__ b_hh,  const float* __restrict__ W_out,
           const float* __restrict__ b_out, float* __restrict__ Y)
{
    // h double buffer, DUPLICATED per entry: hbuf[buf][b][k] = (h[k], h[k])
    __shared__ __align__(16) ull hbuf[2][2][HROW];

    const int lane = threadIdx.x;
    const int jp   = lane & 15;            // hidden-unit pair index
    const int b    = lane >> 4;            // which of this warp's 2 batches
    const int j0   = 2 * jp, j1 = j0 + 1;
    const int batch = blockIdx.x * 2 + b;

    const float SC = 2.8853900817779268f;  // 2*log2(e), folded into weights

    // ---- weights in registers, packed over (j0, j1), pre-scaled by SC ----
    ull w2[HID];
#pragma unroll
    for (int k = 0; k < HID; k++) {
        float a = (j0 < HID) ? SC * W_hh[j0 * HID + k] : 0.0f;
        float c = (j1 < HID) ? SC * W_hh[j1 * HID + k] : 0.0f;
        w2[k] = pk2(a, c);
    }
    const ull wih2 = pk2((j0 < HID) ? SC * W_ih[j0] : 0.0f,
                         (j1 < HID) ? SC * W_ih[j1] : 0.0f);
    const ull bias2 = pk2((j0 < HID) ? SC * (b_ih[j0] + b_hh[j0]) : 0.0f,
                          (j1 < HID) ? SC * (b_ih[j1] + b_hh[j1]) : 0.0f);
    const float wo0 = (j0 < HID) ? W_out[j0] : 0.0f;
    const float wo1 = (j1 < HID) ? W_out[j1] : 0.0f;
    const float bo  = b_out[0];

    // ---- h0 = 0 ----
    hbuf[0][b][j0] = 0ull;
    hbuf[0][b][j1] = 0ull;
    __syncwarp();

    const float* Xb = X + batch;
    float*       Yb = Y + batch;

    // ---- deep X prefetch ring: PF outstanding loads ----
    float xbuf[PF];
#pragma unroll
    for (int i = 0; i < PF; i++) xbuf[i] = Xb[i * BATCH];

    float pp = 0.0f;                 // y partial, reduced one step late

    for (int s0 = 0; s0 < SEQ; s0 += PF) {
        const float* Xpf = Xb + (s0 + PF) * BATCH;
        const bool more = (s0 + PF) < SEQ;

#pragma unroll
        for (int u = 0; u < PF; u++) {
            const int s = s0 + u;
            const ull* hc = &hbuf[u & 1][b][0];        // s&1 == u&1 (PF even)
            ull*       hn = &hbuf[(u & 1) ^ 1][b][0];

            // ---- previous step's y: butterfly-reduce over 16 jp lanes ----
            float r = pp;
#pragma unroll
            for (int m = 1; m < 16; m <<= 1)
                r += __shfl_xor_sync(0xffffffffu, r, m);
            if (jp == 0 && s > 0) Yb[(s - 1) * BATCH] = r + bo;

            // ---- consume x, refill slot PF steps ahead ----
            const float xc = xbuf[u];
            if (more) xbuf[u] = Xpf[u * BATCH];

            // ---- matvec with 4 split accumulator chains ----
            ull a0 = bias2, a1 = 0ull, a2 = 0ull, a3 = 0ull;
#pragma unroll
            for (int i = 0; i < 15; i++) {
                ulonglong2 hv = *(const ulonglong2*)&hc[2 * i];
                if (i & 1) {
                    a2 = ffma2(w2[2 * i],     hv.x, a2);
                    a3 = ffma2(w2[2 * i + 1], hv.y, a3);
                } else {
                    a0 = ffma2(w2[2 * i],     hv.x, a0);
                    a1 = ffma2(w2[2 * i + 1], hv.y, a1);
                }
            }
            a0 = ffma2(wih2, pk2(xc, xc), a0);
            const ull acc = add2(add2(a0, a2), add2(a1, a3));

            // ---- tanh (input pre-scaled via weights) ----
            float v0, v1;
            unpk2(acc, v0, v1);
            const float h0 = tanh_ps(v0);
            const float h1 = tanh_ps(v1);

            // ---- publish h_{s+1}: one STS.128, duplicated layout ----
            ulonglong2 st;
            st.x = pk2(h0, h0);
            st.y = pk2(h1, h1);
            *(ulonglong2*)&hn[j0] = st;

            // ---- this step's y partial (reduced next iteration) ----
            pp = fmaf(h0, wo0, h1 * wo1);

            __syncwarp();
        }
    }

    // final step's y
    {
        float r = pp;
#pragma unroll
        for (int m = 1; m < 16; m <<= 1)
            r += __shfl_xor_sync(0xffffffffu, r, m);
        if (jp == 0) Yb[(SEQ - 1) * BATCH] = r + bo;
    }
}

extern "C" void kernel_launch(void* const* d_in, const int* in_sizes, int n_in,
                              void* d_out, int out_size)
{
    (void)in_sizes; (void)n_in; (void)out_size;
    rnn_kernel<<<BATCH / 2, 32>>>(
        (const float*)d_in[0],  // X
        (const float*)d_in[1],  // W_ih
        (const float*)d_in[2],  // W_hh
        (const float*)d_in[3],  // b_ih
        (const float*)d_in[4],  // b_hh
        (const float*)d_in[5],  // W_out
        (const float*)d_in[6],  // b_out
        (float*)d_out);
}

// round 7
// speedup vs baseline: 1.4889x; 1.1778x over previous
#include <cuda_runtime.h>

#define SEQ   512
#define BATCH 4096
#define HID   30
#define ROWF  40   // floats per (buf,b) row: 32 loaded (30 h + 2 zero pad) + 8 pad -> disjoint bank quads
#define PF    8    // X prefetch depth

typedef unsigned long long ull;

__device__ __forceinline__ ull pk2(float a, float b) {
    ull r; asm("mov.b64 %0,{%1,%2};" : "=l"(r) : "f"(a), "f"(b)); return r;
}
__device__ __forceinline__ void unpk2(ull v, float& a, float& b) {
    asm("mov.b64 {%0,%1},%2;" : "=f"(a), "=f"(b) : "l"(v));
}
// Packed dual-fp32 FMA / ADD (Blackwell f32x2).
__device__ __forceinline__ ull ffma2(ull a, ull b, ull c) {
    ull d; asm("fma.rn.f32x2 %0,%1,%2,%3;" : "=l"(d) : "l"(a), "l"(b), "l"(c)); return d;
}
__device__ __forceinline__ ull add2(ull a, ull b) {
    ull d; asm("add.rn.f32x2 %0,%1,%2;" : "=l"(d) : "l"(a), "l"(b)); return d;
}

// tanh with PRE-SCALED input (2*log2e folded into weights): tanh = 1 - 2/(exp2(v)+1).
__device__ __forceinline__ float tanh_ps(float v) {
    float e, r;
    asm("ex2.approx.f32 %0, %1;" : "=f"(e) : "f"(v));
    asm("rcp.approx.f32 %0, %1;" : "=f"(r) : "f"(e + 1.0f));
    return fmaf(-2.0f, r, 1.0f);
}

__global__ void __launch_bounds__(32)
rnn_kernel(const float* __restrict__ X,     const float* __restrict__ W_ih,
           const float* __restrict__ W_hh,  const float* __restrict__ b_ih,
           const float* __restrict__ b_hh,  const float* __restrict__ W_out,
           const float* __restrict__ b_out, float* __restrict__ Y)
{
    // h double buffer, NATURAL layout: hbuf[buf][b][k] = h[k] (k 0..29, pad 30..39 = 0)
    __shared__ __align__(16) float hbuf[2][2][ROWF];

    const int lane = threadIdx.x;
    const int jp   = lane & 15;            // hidden-unit pair index (j0 = 2jp, j1 = 2jp+1)
    const int b    = lane >> 4;            // which of this warp's 2 batches
    const int j0   = 2 * jp, j1 = j0 + 1;
    const int batch = blockIdx.x * 2 + b;

    const float SC = 2.8853900817779268f;  // 2*log2(e), folded into pre-tanh weights

    // ---- weights packed over (k even, k odd) per output j: 16 pairs each ----
    ull wa[16], wb[16];                    // wa = row j0, wb = row j1
#pragma unroll
    for (int i = 0; i < 16; i++) {
        const int k0 = 2 * i, k1 = 2 * i + 1;
        float a0 = (j0 < HID && k0 < HID) ? SC * W_hh[j0 * HID + k0] : 0.0f;
        float a1 = (j0 < HID && k1 < HID) ? SC * W_hh[j0 * HID + k1] : 0.0f;
        float c0 = (j1 < HID && k0 < HID) ? SC * W_hh[j1 * HID + k0] : 0.0f;
        float c1 = (j1 < HID && k1 < HID) ? SC * W_hh[j1 * HID + k1] : 0.0f;
        wa[i] = pk2(a0, a1);
        wb[i] = pk2(c0, c1);
    }
    const float wih0 = (j0 < HID) ? SC * W_ih[j0] : 0.0f;
    const float wih1 = (j1 < HID) ? SC * W_ih[j1] : 0.0f;
    const float bi0  = (j0 < HID) ? SC * (b_ih[j0] + b_hh[j0]) : 0.0f;
    const float bi1  = (j1 < HID) ? SC * (b_ih[j1] + b_hh[j1]) : 0.0f;
    const float wo0  = (j0 < HID) ? W_out[j0] : 0.0f;
    const float wo1  = (j1 < HID) ? W_out[j1] : 0.0f;
    const float bo   = b_out[0];

    // ---- zero both buffers incl. pad (pad is read by 128b loads; its weights are 0) ----
#pragma unroll
    for (int i = lane; i < 2 * 2 * ROWF; i += 32)
        (&hbuf[0][0][0])[i] = 0.0f;
    __syncwarp();

    const float* Xb = X + batch;
    float*       Yb = Y + batch;

    // ---- deep X prefetch ring ----
    float xbuf[PF];
#pragma unroll
    for (int i = 0; i < PF; i++) xbuf[i] = Xb[i * BATCH];

    float pp = 0.0f;                 // y partial, reduced one step late

    for (int s0 = 0; s0 < SEQ; s0 += PF) {
        const float* Xpf = Xb + (s0 + PF) * BATCH;
        const bool more = (s0 + PF) < SEQ;

#pragma unroll
        for (int u = 0; u < PF; u++) {
            const int s = s0 + u;
            const float4* hc = (const float4*)&hbuf[u & 1][b][0];
            float*        hn = &hbuf[(u & 1) ^ 1][b][0];

            // ---- previous step's y: butterfly over 16 lanes (both halves at once) ----
            float r = pp;
#pragma unroll
            for (int m = 1; m < 16; m <<= 1)
                r += __shfl_xor_sync(0xffffffffu, r, m);
            if (jp == 0 && s > 0) Yb[(s - 1) * BATCH] = r + bo;

            // ---- consume x, refill slot PF steps ahead ----
            const float xc = xbuf[u];
            if (more) xbuf[u] = Xpf[u * BATCH];

            // ---- matvec: acc packed over (k even, k odd); 4 split chains ----
            ull a0 = pk2(bi0, 0.0f), a1 = 0ull;   // j0
            ull c0 = pk2(bi1, 0.0f), c1 = 0ull;   // j1
#pragma unroll
            for (int i = 0; i < 8; i++) {
                const float4 f = hc[i];            // h[4i..4i+3], broadcast to 16 lanes
                const ull hlo = pk2(f.x, f.y);     // register-pair reinterpret (no real op)
                const ull hhi = pk2(f.z, f.w);
                a0 = ffma2(wa[2 * i],     hlo, a0);
                a1 = ffma2(wa[2 * i + 1], hhi, a1);
                c0 = ffma2(wb[2 * i],     hlo, c0);
                c1 = ffma2(wb[2 * i + 1], hhi, c1);
            }
            const ull sa = add2(a0, a1);
            const ull sc = add2(c0, c1);
            float sa0, sa1, sc0, sc1;
            unpk2(sa, sa0, sa1);
            unpk2(sc, sc0, sc1);
            const float v0 = fmaf(wih0, xc, sa0 + sa1);
            const float v1 = fmaf(wih1, xc, sc0 + sc1);

            // ---- tanh (input pre-scaled via weights) ----
            const float h0 = tanh_ps(v0);
            const float h1 = tanh_ps(v1);

            // ---- publish h_{s+1}: one STS.64 in natural layout ----
            // lane jp=15 writes exact zeros into pad slots 30/31 (all its weights are 0)
            *(float2*)&hn[j0] = make_float2(h0, h1);

            // ---- this step's y partial (reduced next iteration) ----
            pp = fmaf(h0, wo0, h1 * wo1);

            __syncwarp();
        }
    }

    // final step's y
    {
        float r = pp;
#pragma unroll
        for (int m = 1; m < 16; m <<= 1)
            r += __shfl_xor_sync(0xffffffffu, r, m);
        if (jp == 0) Yb[(SEQ - 1) * BATCH] = r + bo;
    }
}

extern "C" void kernel_launch(void* const* d_in, const int* in_sizes, int n_in,
                              void* d_out, int out_size)
{
    (void)in_sizes; (void)n_in; (void)out_size;
    rnn_kernel<<<BATCH / 2, 32>>>(
        (const float*)d_in[0],  // X
        (const float*)d_in[1],  // W_ih
        (const float*)d_in[2],  // W_hh
        (const float*)d_in[3],  // b_ih
        (const float*)d_in[4],  // b_hh
        (const float*)d_in[5],  // W_out
        (const float*)d_in[6],  // b_out
        (float*)d_out);
}